// round 15
// baseline (speedup 1.0000x reference)
#include <cuda_runtime.h>
#include <cstddef>

// Problem constants
#define NUM_V  100000
#define NUM_R  1000
#define ARITY  3
#define DD     128     // D
#define DI     192     // D + I
#define HH     128     // H
#define BB     4096    // B
#define NN     64      // N

// Scratch (device globals: no allocation allowed)
__device__ float g_Vp[(size_t)NUM_V * HH];   // 51.2 MB
__device__ float g_Rp[(size_t)NUM_R * HH];   // 512 KB
__device__ float g_PE[HH];

using u64 = unsigned long long;

__device__ __forceinline__ u64 bcast2(float a) {
    u64 r;
    asm("mov.b64 %0, {%1, %1};" : "=l"(r) : "f"(a));
    return r;
}
__device__ __forceinline__ void fma2(u64 &d, u64 a, u64 b) {
    asm("fma.rn.f32x2 %0, %1, %2, %3;" : "=l"(d) : "l"(a), "l"(b), "l"(d));
}

// ---------------------------------------------------------------------------
// Kernel B (merged): Vp GEMM + Rp GEMM + PE, one launch, 128 threads/block.
//   bids [0, NB_VP)              : one 32-row Vp tile each (NUM_V = 32*3125)
//   bids [NB_VP, NB_VP+NUM_R)    : one Rp row each
//   bid  NB_VP+NUM_R             : PE block
//
// R14 ncu: vp was ~110us vs 72us FFMA2 floor with only 4 warps/SMSP and 89%
// issue-port demand -> arbiter bubbles. This version shrinks the tile
// (24 KB smem, 128 thr) to get ~6 blocks/SM = 6 warps/SMSP while keeping
// 8 rows/thread (WV l1tex traffic unchanged at 0.5 B/MAC).
// ---------------------------------------------------------------------------
#define VP_ROWS 32
#define VP_RPT  8   // rows per thread
#define NB_VP   (NUM_V / VP_ROWS)   // 3125 (exact)
__global__ __launch_bounds__(128, 6)
void vp_rp_pe_kernel(const float* __restrict__ V,
                     const float* __restrict__ WV,
                     const float* __restrict__ bV,
                     const float* __restrict__ R,
                     const float* __restrict__ WR,
                     const float* __restrict__ bR,
                     const float* __restrict__ P,
                     const float* __restrict__ WP,
                     const float* __restrict__ bP) {
    __shared__ float sV[VP_ROWS][DI];   // 24 KB
    const int tid = threadIdx.x;
    const int bid = blockIdx.x;

    if (bid < NB_VP) {
        // ----------------- Vp tile path -----------------
        const int row0 = bid * VP_ROWS;
        {
            // 32x192 fp32 tile = 1536 float4, 12 per thread. No ragged tile.
            const float4* __restrict__ src =
                reinterpret_cast<const float4*>(V + (size_t)row0 * DI);
            float4* dst = reinterpret_cast<float4*>(&sV[0][0]);
#pragma unroll
            for (int i = 0; i < 12; i++) {
                int idx = tid + i * 128;
                dst[idx] = __ldg(src + idx);
            }
        }
        __syncthreads();

        const int hq = tid & 31;
        const int rg = tid >> 5;           // 0..3; warp owns rows rg*8..rg*8+7
        const int h0 = hq * 4;

        u64 acc[VP_RPT][2];
        {
            ulonglong2 bv = __ldg(reinterpret_cast<const ulonglong2*>(bV + h0));
#pragma unroll
            for (int r = 0; r < VP_RPT; r++) { acc[r][0] = bv.x; acc[r][1] = bv.y; }
        }

        for (int k0 = 0; k0 < DI; k0 += 4) {
            float4 v[VP_RPT];
#pragma unroll
            for (int r = 0; r < VP_RPT; r++)
                v[r] = *reinterpret_cast<const float4*>(&sV[rg * VP_RPT + r][k0]);
#pragma unroll
            for (int kk = 0; kk < 4; kk++) {
                // WV row k, 4 consecutive h -> two packed f32x2 operands
                ulonglong2 w = __ldg(reinterpret_cast<const ulonglong2*>(
                    WV + (size_t)(k0 + kk) * HH + h0));
#pragma unroll
                for (int r = 0; r < VP_RPT; r++) {
                    float vs = (kk == 0) ? v[r].x : (kk == 1) ? v[r].y
                             : (kk == 2) ? v[r].z : v[r].w;
                    u64 vb = bcast2(vs);
                    fma2(acc[r][0], vb, w.x);
                    fma2(acc[r][1], vb, w.y);
                }
            }
        }

#pragma unroll
        for (int r = 0; r < VP_RPT; r++) {
            int row = row0 + rg * VP_RPT + r;
            float4 o;
            reinterpret_cast<u64*>(&o)[0] = acc[r][0];
            reinterpret_cast<u64*>(&o)[1] = acc[r][1];
            *reinterpret_cast<float4*>(g_Vp + (size_t)row * HH + h0) = o;
        }
    } else if (bid < NB_VP + NUM_R) {
        // ----------------- Rp path: 1 row per block -----------------
        const int h   = tid;               // 0..127
        const int row = bid - NB_VP;
        float* sR = &sV[0][0];
        sR[h] = __ldg(R + row * DD + h);
        __syncthreads();
        float acc = __ldg(bR + h);
#pragma unroll 8
        for (int k = 0; k < DD; k++)
            acc = fmaf(sR[k], __ldg(WR + k * HH + h), acc);
        g_Rp[(size_t)row * HH + h] = acc;
    } else {
        // ----------------- PE path -----------------
        const int h = tid;
        float prod = 1.0f;
#pragma unroll
        for (int a = 0; a < ARITY; a++) {
            float acc = __ldg(bP + h);
#pragma unroll 8
            for (int k = 0; k < DD; k++)
                acc = fmaf(__ldg(P + a * DD + k), __ldg(WP + k * HH + h), acc);
            prod *= acc;
        }
        g_PE[h] = prod;
    }
}

// ---------------------------------------------------------------------------
// Kernel C: out[b,h] = PE[h] * sum_n Rp[r[b,n],h] * Vp[e0,h]*Vp[e1,h]*Vp[e2,h]
// FROZEN: R14 ncu shows 30.8us = NAT-clock LTS floor (L2 69%, DRAM 23%,
// ~89% L2 hit on the gathers). Nothing left on the table here.
// ---------------------------------------------------------------------------
#define C_BPB 4
__global__ __launch_bounds__(128, 8)
void gather_kernel(const int* __restrict__ r,
                   const int* __restrict__ e,
                   float* __restrict__ out) {
    __shared__ int4 sOff[C_BPB * NN];   // 4 KB: {rp_off, v0_off, v1_off, v2_off}
    const int tid = threadIdx.x;
    const int b0 = blockIdx.x * C_BPB;

    // Cooperative index load; pre-scale to byte offsets (row * 512B)
    for (int i = tid; i < C_BPB * NN; i += 128) {
        int g = b0 * NN + i;
        int4 o;
        o.x = __ldg(r + g)               << 9;
        o.y = __ldg(e + 0 * BB * NN + g) << 9;
        o.z = __ldg(e + 1 * BB * NN + g) << 9;
        o.w = __ldg(e + 2 * BB * NN + g) << 9;
        sOff[i] = o;
    }
    __syncthreads();

    const int bl = tid >> 5;
    const int h0 = (tid & 31) * 4;

    const char* __restrict__ rpB = reinterpret_cast<const char*>(g_Rp) + h0 * 4;
    const char* __restrict__ vpB = reinterpret_cast<const char*>(g_Vp) + h0 * 4;

    float4 acc = make_float4(0.f, 0.f, 0.f, 0.f);
#pragma unroll 4
    for (int n = 0; n < NN; n++) {
        const int4 o = sOff[bl * NN + n];
        const float4 rp = __ldg(reinterpret_cast<const float4*>(rpB + o.x));
        const float4 v0 = __ldg(reinterpret_cast<const float4*>(vpB + o.y));
        const float4 v1 = __ldg(reinterpret_cast<const float4*>(vpB + o.z));
        const float4 v2 = __ldg(reinterpret_cast<const float4*>(vpB + o.w));
        acc.x = fmaf(rp.x * v0.x, v1.x * v2.x, acc.x);
        acc.y = fmaf(rp.y * v0.y, v1.y * v2.y, acc.y);
        acc.z = fmaf(rp.z * v0.z, v1.z * v2.z, acc.z);
        acc.w = fmaf(rp.w * v0.w, v1.w * v2.w, acc.w);
    }

    const float4 pe = __ldg(reinterpret_cast<const float4*>(g_PE + h0));
    float4 o = make_float4(acc.x * pe.x, acc.y * pe.y,
                           acc.z * pe.z, acc.w * pe.w);
    *reinterpret_cast<float4*>(out + (size_t)(b0 + bl) * HH + h0) = o;
}

// ---------------------------------------------------------------------------
// Launch. Inputs (metadata order): r, e, V, R, P, WV, bV, WR, bR, WP, bP
// ---------------------------------------------------------------------------
extern "C" void kernel_launch(void* const* d_in, const int* in_sizes, int n_in,
                              void* d_out, int out_size) {
    const int*   r  = (const int*)  d_in[0];
    const int*   e  = (const int*)  d_in[1];
    const float* V  = (const float*)d_in[2];
    const float* R  = (const float*)d_in[3];
    const float* P  = (const float*)d_in[4];
    const float* WV = (const float*)d_in[5];
    const float* bV = (const float*)d_in[6];
    const float* WR = (const float*)d_in[7];
    const float* bR = (const float*)d_in[8];
    const float* WP = (const float*)d_in[9];
    const float* bP = (const float*)d_in[10];
    float* out = (float*)d_out;

    vp_rp_pe_kernel<<<NB_VP + NUM_R + 1, 128>>>(V, WV, bV, R, WR, bR, P, WP, bP);
    gather_kernel<<<BB / C_BPB, 128>>>(r, e, out);
}